// round 17
// baseline (speedup 1.0000x reference)
#include <cuda_runtime.h>
#include <cuda_fp16.h>
#include <math.h>
#include <stdint.h>

#define BATCH 16
#define CINC 64
#define HH 128
#define WW 128
#define HW 16384
#define NCLS 80
#define KTOP 100

// ---------------- device scratch ----------------
__device__ float g_featc[BATCH * HW * 64];       // relu(conv3x3), CHANNEL-LAST [b][h][w][oc]
__device__ unsigned int g_scoreu[BATCH * HW];    // monotone-uint masked logit
__device__ int   g_cat  [BATCH * HW];
__device__ float g_tscore[BATCH * KTOP];         // logit of selected
__device__ int   g_tind  [BATCH * KTOP];
__device__ float g_boxes[BATCH * KTOP * 4];

// fp16 split input (x*16): [s in {0,1}][b*128+R][px*64+cin] (8192 elems/row)
#define XS_ELEMS_PER_SPLIT ((size_t)BATCH * 128 * 8192)
__device__ __half g_xs[2 * XS_ELEMS_PER_SPLIT];
// pre-swizzled fp16 split weights (w*64): [pass*9+tap][4096 elems, SW128]
__device__ __half g_wsw[18 * 4096];

#define SW128(o) ((o) ^ (((o) >> 3) & 0x70))
#define OUT_SCALE (1.f / 1024.f)

// ---------------- f32x2 helpers (clspeak) ----------------
__device__ __forceinline__ unsigned long long fma2(unsigned long long a, unsigned long long b,
                                                   unsigned long long c) {
    unsigned long long d;
    asm("fma.rn.f32x2 %0, %1, %2, %3;" : "=l"(d) : "l"(a), "l"(b), "l"(c));
    return d;
}
__device__ __forceinline__ float2 upk(unsigned long long v) {
    unsigned int a, b;
    asm("mov.b64 {%0, %1}, %2;" : "=r"(a), "=r"(b) : "l"(v));
    return make_float2(__uint_as_float(a), __uint_as_float(b));
}

// ---------------- warp-mma / cp.async helpers ----------------
__device__ __forceinline__ uint32_t smem_u32(const void* p) {
    uint32_t a;
    asm("{ .reg .u64 t; cvta.to.shared.u64 t, %1; cvt.u32.u64 %0, t; }" : "=r"(a) : "l"(p));
    return a;
}
__device__ __forceinline__ void ldsm_x4(uint32_t* r, uint32_t addr) {
    asm volatile("ldmatrix.sync.aligned.m8n8.x4.shared.b16 {%0,%1,%2,%3}, [%4];"
        : "=r"(r[0]), "=r"(r[1]), "=r"(r[2]), "=r"(r[3]) : "r"(addr));
}
__device__ __forceinline__ void mma16816(float* d, const uint32_t* a, const uint32_t* b) {
    asm volatile(
        "mma.sync.aligned.m16n8k16.row.col.f32.f16.f16.f32 "
        "{%0,%1,%2,%3}, {%4,%5,%6,%7}, {%8,%9}, {%0,%1,%2,%3};"
        : "+f"(d[0]), "+f"(d[1]), "+f"(d[2]), "+f"(d[3])
        : "r"(a[0]), "r"(a[1]), "r"(a[2]), "r"(a[3]), "r"(b[0]), "r"(b[1]));
}
__device__ __forceinline__ void cp_async16(uint32_t dst, const void* src, bool valid) {
    int sz = valid ? 16 : 0;
    asm volatile("cp.async.cg.shared.global [%0], [%1], 16, %2;"
                 :: "r"(dst), "l"(src), "r"(sz) : "memory");
}
__device__ __forceinline__ void cp_commit() {
    asm volatile("cp.async.commit_group;" ::: "memory");
}
__device__ __forceinline__ void cp_wait_all() {
    asm volatile("cp.async.wait_group 0;" ::: "memory");
}

// =====================================================================
// Prep 1: split x*16 into 2 fp16 parts, layout [s][b*128+R][px*64+cin]
// =====================================================================
__global__ __launch_bounds__(256) void xsplit_kernel(const float* __restrict__ x)
{
    __shared__ float tile[64 * 128];
    const int R = blockIdx.x, b = blockIdx.y;
    const int tid = threadIdx.x;

    for (int e = tid; e < 8192; e += 256) {
        int cin = e >> 7, px = e & 127;
        tile[e] = x[((size_t)(b * 64 + cin) * 128 + R) * 128 + px];
    }
    __syncthreads();

    const size_t rowbase = ((size_t)b * 128 + R) * 8192;
    for (int e = tid; e < 4096; e += 256) {
        int e2 = e * 2;
        int px = e2 >> 6, cin0 = e2 & 63;
        float f0 = tile[cin0 * 128 + px] * 16.f;
        float f1 = tile[(cin0 + 1) * 128 + px] * 16.f;
        __half h10 = __float2half_rn(f0);
        __half h11 = __float2half_rn(f1);
        __half h20 = __float2half_rn(f0 - __half2float(h10));
        __half h21 = __float2half_rn(f1 - __half2float(h11));
        size_t eb = rowbase + e2;
        g_xs[eb] = h10; g_xs[eb + 1] = h11;
        g_xs[XS_ELEMS_PER_SPLIT + eb]     = h20;
        g_xs[XS_ELEMS_PER_SPLIT + eb + 1] = h21;
    }
}

// =====================================================================
// Prep 2: split + pre-swizzle weights (w*64): g_wsw[pass*9+tap]
// =====================================================================
__global__ __launch_bounds__(256) void wprep_kernel(const float* __restrict__ w1)
{
    const int t = blockIdx.x;          // 0..17 = pass*9 + tap
    const int pass = t / 9, tap = t - pass * 9;
    const int tid = threadIdx.x;
    for (int e = tid; e < 4096; e += 256) {
        int oc = e >> 6, cin = e & 63;
        float f = w1[oc * 576 + cin * 9 + tap] * 64.f;
        __half h1 = __float2half_rn(f);
        __half out = pass ? __float2half_rn(f - __half2float(h1)) : h1;
        uint32_t o = SW128((uint32_t)e * 2);
        g_wsw[(size_t)t * 4096 + (o >> 1)] = out;
    }
}

// =====================================================================
// conv via warp-level mma.sync (fp16, 4-term), single fused kernel.
// Grid (16 rowgroups, 2 oc-halves, 16 batches); 512 threads / 16 warps.
// Output: CHANNEL-LAST g_featc[b][y][px][oc], paired float2 stores.
// =====================================================================
#define BT_OFF 0u
#define AT_OFF 73728u
#define SLOT_STRIDE 33792u
#define SPLIT_STRIDE 16896u
#define CONVM_SMEM (73728 + 4 * 33792)
#define CONV_THREADS 512

__device__ __forceinline__ void cp_a_row(char* smem, int b, int R, int slot, int tid) {
    #pragma unroll
    for (int j = 0; j < 5; j++) {
        int c = j * CONV_THREADS + tid;
        if (c < 2080) {
            int s = (c >= 1040) ? 1 : 0;
            int r = c - s * 1040;
            int px_dst = r >> 3;
            int w16 = (r & 7) * 16;
            int px_src = px_dst - 1;
            bool valid = (R >= 0 && R < 128 && px_src >= 0 && px_src < 128);
            const char* src = (const char*)g_xs
                + (size_t)s * XS_ELEMS_PER_SPLIT * 2
                + (valid ? ((((size_t)b * 128 + R) * 8192 + (size_t)px_src * 64) * 2 + w16) : 0);
            uint32_t o = ((uint32_t)px_dst) * 128 + (uint32_t)w16;
            uint32_t dst = smem_u32(smem + AT_OFF + slot * SLOT_STRIDE
                                    + s * SPLIT_STRIDE + SW128(o));
            cp_async16(dst, src, valid);
        }
    }
}

__global__ __launch_bounds__(CONV_THREADS, 1) void conv_mma_kernel(const float* __restrict__ b1)
{
    extern __shared__ char smem[];
    const uint32_t sb = smem_u32(smem);
    const int g = blockIdx.x, ochalf = blockIdx.y, b = blockIdx.z;
    const int tid = threadIdx.x;
    const int w = tid >> 5, lane = tid & 31;
    const int wpx = w & 7;
    const int woc = w >> 3;
    const int Y0 = g * 8;
    const int q = lane >> 3, rr = lane & 7;

    const uint32_t a_row = (uint32_t)(wpx * 16 + rr + 8 * (q & 1));
    const uint32_t a_sub = (uint32_t)(16 * (q >> 1));
    const uint32_t b_base = (uint32_t)((8 * (q >> 1) + rr) * 128 + 16 * (q & 1))
                          + (uint32_t)woc * 2048u;
    const int px0 = wpx * 16 + (lane >> 2);
    const int oc0 = ochalf * 32 + woc * 16 + 2 * (lane & 3);
    float* gout = g_featc + (size_t)b * HW * 64;

    for (int idx = tid; idx < 4608; idx += CONV_THREADS) {
        int t = idx >> 8;
        int u = idx & 255;
        *(uint4*)(smem + BT_OFF + (uint32_t)(t * 4096 + u * 16)) =
            __ldg((const uint4*)((const char*)g_wsw + (size_t)t * 8192
                                 + (size_t)ochalf * 4096 + (size_t)u * 16));
    }
    for (int R = Y0 - 1; R <= Y0 + 1; R++) {
        cp_a_row(smem, b, R, (R + 1) & 3, tid);
    }
    cp_commit();
    cp_wait_all();
    __syncthreads();

    for (int r0 = 0; r0 < 8; r0++) {
        const int y = Y0 + r0;
        if (r0 < 7) {
            cp_a_row(smem, b, y + 2, (y + 3) & 3, tid);
            cp_commit();
        }

        float acc[2][4];
        #pragma unroll
        for (int i = 0; i < 2; i++)
            #pragma unroll
            for (int j = 0; j < 4; j++) acc[i][j] = 0.f;

        #pragma unroll
        for (int ky = 0; ky < 3; ky++) {
            const uint32_t slotb = sb + AT_OFF + (uint32_t)(((y + ky) & 3) * SLOT_STRIDE);
            #pragma unroll
            for (int kc = 0; kc < 4; kc++) {
                #pragma unroll
                for (int kx = 0; kx < 3; kx++) {
                    uint32_t o = (a_row + kx) * 128 + a_sub + 32 * kc;
                    uint32_t a1f[4], a2f[4];
                    ldsm_x4(a1f, slotb + SW128(o));
                    ldsm_x4(a2f, slotb + SPLIT_STRIDE + SW128(o));
                    const uint32_t boff = SW128(b_base + 32 * kc);
                    const uint32_t tile1 = sb + BT_OFF + (uint32_t)((ky * 3 + kx) * 4096);
                    const uint32_t tile2 = tile1 + 9u * 4096u;
                    uint32_t bw1[4], bw2[4];
                    ldsm_x4(bw1, tile1 + boff);
                    ldsm_x4(bw2, tile2 + boff);
                    mma16816(acc[0], a1f, bw1);
                    mma16816(acc[1], a1f, bw1 + 2);
                    mma16816(acc[0], a2f, bw1);
                    mma16816(acc[1], a2f, bw1 + 2);
                    mma16816(acc[0], a1f, bw2);
                    mma16816(acc[1], a1f, bw2 + 2);
                    mma16816(acc[0], a2f, bw2);
                    mma16816(acc[1], a2f, bw2 + 2);
                }
            }
        }

        // epilogue: channel-last paired stores
        #pragma unroll
        for (int nt = 0; nt < 2; nt++) {
            const int oc = oc0 + nt * 8;
            const float ba = __ldg(b1 + oc), bbv = __ldg(b1 + oc + 1);
            float2 v0, v1;
            v0.x = fmaxf(acc[nt][0] * OUT_SCALE + ba,  0.f);
            v0.y = fmaxf(acc[nt][1] * OUT_SCALE + bbv, 0.f);
            v1.x = fmaxf(acc[nt][2] * OUT_SCALE + ba,  0.f);
            v1.y = fmaxf(acc[nt][3] * OUT_SCALE + bbv, 0.f);
            *(float2*)(gout + ((size_t)(y * 128 + px0)     * 64 + oc)) = v0;
            *(float2*)(gout + ((size_t)(y * 128 + px0 + 8) * 64 + oc)) = v1;
        }
        cp_wait_all();
        __syncthreads();
    }
}

// =====================================================================
// Fused 1x1 conv (64->80) + LOGIT-SPACE 3x3 peak + argmax.
// Channel-last feat: fd[i] is a direct 8B load (two consecutive floats
// = packed f32x2). 16 x 16B loads per thread, fully coalesced sectors.
// =====================================================================
__global__ __launch_bounds__(128, 4) void clspeak_kernel(
    const float* __restrict__ w2, const float* __restrict__ b2)
{
    __shared__ float s_w[80 * 64];
    __shared__ float s_b[80];
    __shared__ float s_cls[20 * 104];

    const int bx = blockIdx.x, by = blockIdx.y, b = blockIdx.z;
    const int ox = bx * 8, oy = by * 8;
    const int tid = threadIdx.x;
    const float NEG = -1e30f;

    for (int e = tid; e < 80 * 64; e += 128) s_w[e] = w2[e];
    if (tid < 80) s_b[tid] = b2[tid];

    unsigned long long fd[32];
    bool inimg = false;
    if (tid < 100) {
        int iy = tid / 10, ix = tid - iy * 10;
        int gy = oy + iy - 1, gx = ox + ix - 1;
        inimg = (gy >= 0 && gy < HH && gx >= 0 && gx < WW);
        const unsigned long long* fp = (const unsigned long long*)
            (g_featc + ((size_t)b * HW + (inimg ? (gy * WW + gx) : 0)) * 64);
        #pragma unroll
        for (int i = 0; i < 16; i++) {
            ulonglong2 v = inimg ? ((const ulonglong2*)fp)[i] : make_ulonglong2(0ull, 0ull);
            fd[2 * i]     = v.x;
            fd[2 * i + 1] = v.y;
        }
    }
    __syncthreads();

    const int py = (tid >> 3) + 1, px = (tid & 7) + 1;
    const int pp = py * 10 + px;
    float best = NEG;
    int cat = 0;

    for (int g = 0; g < 4; g++) {
        if (tid < 100) {
            #pragma unroll
            for (int cp = 0; cp < 10; cp++) {
                const int c0 = g * 20 + 2 * cp;
                unsigned long long a0 = 0ull, a1 = 0ull;
                const ulonglong2* w0 = (const ulonglong2*)(s_w + c0 * 64);
                const ulonglong2* w1 = (const ulonglong2*)(s_w + (c0 + 1) * 64);
                #pragma unroll
                for (int i = 0; i < 16; i++) {
                    ulonglong2 wa = w0[i];
                    ulonglong2 wb = w1[i];
                    a0 = fma2(fd[2 * i],     wa.x, a0);
                    a0 = fma2(fd[2 * i + 1], wa.y, a0);
                    a1 = fma2(fd[2 * i],     wb.x, a1);
                    a1 = fma2(fd[2 * i + 1], wb.y, a1);
                }
                float2 u0 = upk(a0), u1 = upk(a1);
                float v0 = u0.x + u0.y + s_b[c0];
                float v1 = u1.x + u1.y + s_b[c0 + 1];
                if (!inimg) { v0 = NEG; v1 = NEG; }
                s_cls[(2 * cp)     * 104 + tid] = v0;
                s_cls[(2 * cp + 1) * 104 + tid] = v1;
            }
        }
        __syncthreads();
        if (tid < 64) {
            #pragma unroll 4
            for (int c = 0; c < 20; c++) {
                const float* row = s_cls + c * 104;
                float v = row[pp];
                float m = v;
                m = fmaxf(m, row[pp - 11]); m = fmaxf(m, row[pp - 10]); m = fmaxf(m, row[pp - 9]);
                m = fmaxf(m, row[pp - 1]);                               m = fmaxf(m, row[pp + 1]);
                m = fmaxf(m, row[pp + 9]);  m = fmaxf(m, row[pp + 10]); m = fmaxf(m, row[pp + 11]);
                float k = (v == m) ? v : NEG;
                if (k > best) { best = k; cat = g * 20 + c; }
            }
        }
        __syncthreads();
    }

    if (tid < 64) {
        int gp = (oy + py - 1) * WW + ox + px - 1;
        unsigned int u = __float_as_uint(best);
        unsigned int mu = (u & 0x80000000u) ? ~u : (u | 0x80000000u);
        g_scoreu[b * HW + gp] = mu;
        g_cat[b * HW + gp]    = cat;
    }
}

// =====================================================================
// top-100 on monotone-uint keys; writes back logits.
// =====================================================================
#define TOPK_SMEM (8192 * 4 + 1024 * 4 + HW * 8)
__global__ __launch_bounds__(1024) void topk_kernel()
{
    extern __shared__ int smi[];
    int* hist = smi;
    int* suf  = smi + 8192;
    unsigned long long* cand = (unsigned long long*)(smi + 8192 + 1024);
    __shared__ int s_tstar, s_T, s_cnt;

    const int b = blockIdx.x;
    const int tid = threadIdx.x;
    const unsigned int* s = g_scoreu + b * HW;

    for (int i = tid; i < 8192; i += 1024) hist[i] = 0;
    if (tid == 0) s_cnt = 0;
    __syncthreads();

    for (int j = tid; j < HW; j += 1024) {
        unsigned int mu = s[j];
        atomicAdd(&hist[mu >> 19], 1);
    }
    __syncthreads();

    int seg = 0;
    #pragma unroll
    for (int k = 0; k < 8; k++) seg += hist[tid * 8 + k];
    suf[tid] = seg;
    __syncthreads();
    for (int off = 1; off < 1024; off <<= 1) {
        int v = suf[tid];
        int add = (tid + off < 1024) ? suf[tid + off] : 0;
        __syncthreads();
        suf[tid] = v + add;
        __syncthreads();
    }
    if (suf[tid] >= KTOP && (tid == 1023 || suf[tid + 1] < KTOP)) s_tstar = tid;
    __syncthreads();
    if (tid == s_tstar) {
        int acc = (tid == 1023) ? 0 : suf[tid + 1];
        for (int bb = tid * 8 + 7; bb >= tid * 8; bb--) {
            acc += hist[bb];
            if (acc >= KTOP) { s_T = bb; break; }
        }
    }
    __syncthreads();
    const int T = s_T;

    for (int j = tid; j < HW; j += 1024) {
        unsigned int mu = s[j];
        if ((int)(mu >> 19) >= T) {
            int pos = atomicAdd(&s_cnt, 1);
            cand[pos] = ((unsigned long long)mu << 32) | (unsigned long long)(HW - j);
        }
    }
    __syncthreads();
    const int N = s_cnt;

    for (int i = tid; i < N; i += 1024) {
        unsigned long long key = cand[i];
        int rank = 0;
        for (int j = 0; j < N; j++) rank += (cand[j] > key);
        if (rank < KTOP) {
            unsigned int mu = (unsigned int)(key >> 32);
            unsigned int u = (mu & 0x80000000u) ? (mu ^ 0x80000000u) : ~mu;
            g_tscore[b * KTOP + rank] = __uint_as_float(u);
            g_tind[b * KTOP + rank]   = HW - (int)(key & 0xFFFFFFFFull);
        }
    }
}

// =====================================================================
// reg/wh at selected points (PTS=2)
// =====================================================================
#define PTS 2
__global__ __launch_bounds__(128) void point_kernel(
    const float* __restrict__ x,
    const float* __restrict__ rw1, const float* __restrict__ rb1,
    const float* __restrict__ rw2, const float* __restrict__ rb2,
    const float* __restrict__ ww1, const float* __restrict__ wb1,
    const float* __restrict__ ww2, const float* __restrict__ wb2)
{
    __shared__ float sx[PTS][576];
    __shared__ int   sp[PTS];
    __shared__ float sfa[128][PTS + 1];
    __shared__ float sres[PTS][4];

    const int g = blockIdx.x, b = blockIdx.y;
    const int tid = threadIdx.x;

    if (tid < PTS) sp[tid] = g_tind[b * KTOP + g * PTS + tid];
    __syncthreads();

    for (int e = tid; e < PTS * 576; e += 128) {
        int pt = e / 576;
        int r  = e - pt * 576;
        int c  = r / 9;
        int k9 = r - c * 9;
        int dy = k9 / 3 - 1, dx = k9 % 3 - 1;
        int p = sp[pt];
        int gy = (p >> 7) + dy, gx = (p & 127) + dx;
        float v = 0.f;
        if (gy >= 0 && gy < HH && gx >= 0 && gx < WW)
            v = x[((size_t)b * CINC + c) * HW + gy * WW + gx];
        sx[pt][r] = v;
    }
    __syncthreads();

    const float* wrow = (tid < 64) ? (rw1 + tid * 576) : (ww1 + (tid - 64) * 576);
    float bias = (tid < 64) ? rb1[tid] : wb1[tid - 64];
    float acc[PTS];
    #pragma unroll
    for (int pt = 0; pt < PTS; pt++) acc[pt] = bias;

    for (int j = 0; j < 576; j += 4) {
        float4 w4 = *(const float4*)(wrow + j);
        #pragma unroll
        for (int q = 0; q < 4; q++) {
            float w = (q == 0) ? w4.x : (q == 1) ? w4.y : (q == 2) ? w4.z : w4.w;
            #pragma unroll
            for (int pt = 0; pt < PTS; pt++)
                acc[pt] = fmaf(w, sx[pt][j + q], acc[pt]);
        }
    }
    #pragma unroll
    for (int pt = 0; pt < PTS; pt++) sfa[tid][pt] = fmaxf(acc[pt], 0.f);
    __syncthreads();

    if (tid < PTS * 4) {
        int pt = tid >> 2, o = tid & 3;
        float sv;
        if (o < 2) {
            sv = rb2[o];
            for (int i = 0; i < 64; i++) sv = fmaf(sfa[i][pt], rw2[o * 64 + i], sv);
            sv = 1.f / (1.f + expf(-sv));
        } else {
            int oo = o - 2;
            sv = wb2[oo];
            for (int i = 0; i < 64; i++) sv = fmaf(sfa[64 + i][pt], ww2[oo * 64 + i], sv);
            sv = expf(sv);
        }
        sres[pt][o] = sv;
    }
    __syncthreads();

    if (tid < PTS) {
        int p = sp[tid];
        float cx = (float)(p & 127) + sres[tid][0];
        float cy = (float)(p >> 7)  + sres[tid][1];
        float wv = sres[tid][2], hv = sres[tid][3];
        int k = b * KTOP + g * PTS + tid;
        g_boxes[k * 4 + 0] = (cx - wv * 0.5f) * 4.f;
        g_boxes[k * 4 + 1] = (cy - hv * 0.5f) * 4.f;
        g_boxes[k * 4 + 2] = (cx + wv * 0.5f) * 4.f;
        g_boxes[k * 4 + 3] = (cy + hv * 0.5f) * 4.f;
    }
}

// =====================================================================
// NMS + output (sigmoid applied here to the selected logits)
// =====================================================================
__global__ __launch_bounds__(128) void nms_kernel(float* __restrict__ out)
{
    const int b = blockIdx.x;
    const int tid = threadIdx.x;
    __shared__ float bx[KTOP][4];
    __shared__ float barea[KTOP];
    __shared__ int keep[KTOP];

    float score = 0.f; int cat = 0;
    if (tid < KTOP) {
        int k = b * KTOP + tid;
        float logit = g_tscore[k];
        score = 1.f / (1.f + expf(-logit));
        cat   = g_cat[b * HW + g_tind[k]];
        float x1 = g_boxes[k * 4 + 0], y1 = g_boxes[k * 4 + 1];
        float x2 = g_boxes[k * 4 + 2], y2 = g_boxes[k * 4 + 3];
        bx[tid][0] = x1; bx[tid][1] = y1; bx[tid][2] = x2; bx[tid][3] = y2;
        barea[tid] = (x2 - x1) * (y2 - y1);
        keep[tid] = (score > 0.2f) ? 1 : 0;
    }
    __syncthreads();

    for (int i = 0; i < KTOP - 1; i++) {
        if (tid < KTOP && tid > i && keep[i]) {
            float xx1 = fmaxf(bx[i][0], bx[tid][0]);
            float yy1 = fmaxf(bx[i][1], bx[tid][1]);
            float xx2 = fminf(bx[i][2], bx[tid][2]);
            float yy2 = fminf(bx[i][3], bx[tid][3]);
            float iw = fmaxf(xx2 - xx1, 0.f);
            float ih = fmaxf(yy2 - yy1, 0.f);
            float inter = iw * ih;
            float iou = inter / (barea[i] + barea[tid] - inter + 1e-9f);
            if (iou > 0.5f) keep[tid] = 0;
        }
        __syncthreads();
    }

    if (tid < KTOP) {
        int base = b * KTOP + tid;
        out[base * 4 + 0] = bx[tid][0];
        out[base * 4 + 1] = bx[tid][1];
        out[base * 4 + 2] = bx[tid][2];
        out[base * 4 + 3] = bx[tid][3];
        out[6400 + base] = (float)cat;
        out[8000 + base] = score;
        out[9600 + base] = keep[tid] ? 1.f : 0.f;
    }
}

// =====================================================================
extern "C" void kernel_launch(void* const* d_in, const int* in_sizes, int n_in,
                              void* d_out, int out_size)
{
    const float* x      = (const float*)d_in[0];
    const float* cls_w1 = (const float*)d_in[1];
    const float* cls_b1 = (const float*)d_in[2];
    const float* cls_w2 = (const float*)d_in[3];
    const float* cls_b2 = (const float*)d_in[4];
    const float* reg_w1 = (const float*)d_in[5];
    const float* reg_b1 = (const float*)d_in[6];
    const float* reg_w2 = (const float*)d_in[7];
    const float* reg_b2 = (const float*)d_in[8];
    const float* wh_w1  = (const float*)d_in[9];
    const float* wh_b1  = (const float*)d_in[10];
    const float* wh_w2  = (const float*)d_in[11];
    const float* wh_b2  = (const float*)d_in[12];
    float* out = (float*)d_out;

    cudaFuncSetAttribute(conv_mma_kernel, cudaFuncAttributeMaxDynamicSharedMemorySize, CONVM_SMEM);
    cudaFuncSetAttribute(topk_kernel, cudaFuncAttributeMaxDynamicSharedMemorySize, TOPK_SMEM);

    xsplit_kernel<<<dim3(128, BATCH), 256>>>(x);
    wprep_kernel<<<18, 256>>>(cls_w1);
    conv_mma_kernel<<<dim3(16, 2, BATCH), CONV_THREADS, CONVM_SMEM>>>(cls_b1);
    clspeak_kernel<<<dim3(16, 16, BATCH), 128>>>(cls_w2, cls_b2);
    topk_kernel<<<BATCH, 1024, TOPK_SMEM>>>();
    point_kernel<<<dim3(50, BATCH), 128>>>(x, reg_w1, reg_b1, reg_w2, reg_b2,
                                           wh_w1, wh_b1, wh_w2, wh_b2);
    nms_kernel<<<BATCH, 128>>>(out);
}